// round 2
// baseline (speedup 1.0000x reference)
#include <cuda_runtime.h>
#include <math.h>

#define NE   64      // num experts
#define TK   8       // top-k
#define DIM  2048    // hidden dim
#define TM   128     // tokens per block
#define KB   32      // k-chunk
#define NIT  (DIM / KB)

#define XS_STRIDE 132        // mult of 4 (16B-aligned packed loads), 4-way STS conflict max
#define WS_STRIDE 64
#define LS_STRIDE 68

__device__ __align__(16) float g_bias[NE];
__device__ float g_nbs;
__device__ float g_acc[NE];

// ---------------------------------------------------------------------------
// Prep: adaptive bias from expert loads (depends only on inputs), zero accum.
// ---------------------------------------------------------------------------
__global__ void k_prep(const float* __restrict__ loads, const float* __restrict__ bs)
{
    int e = threadIdx.x;
    __shared__ float s[NE];
    s[e] = loads[e];
    __syncthreads();

    float sum = 0.f;
    #pragma unroll
    for (int i = 0; i < NE; i++) sum += s[i];
    sum = fmaxf(sum, 1e-8f);

    const float t = 1.0f / (float)NE;
    float kl = 0.f;
    #pragma unroll
    for (int i = 0; i < NE; i++) {
        float q = s[i] / sum;
        kl += t * (logf(t) - logf(fmaxf(q, 1e-8f)));
    }
    float adaptive = 1.0f / (1.0f + expf(-10.0f * kl));
    float nbs = 0.9f * bs[0] + 0.1f * adaptive;

    float q = s[e] / sum;
    g_bias[e] = tanhf((q - t) * (float)NE) * nbs;
    g_acc[e] = 0.f;
    if (e == 0) g_nbs = nbs;
}

// ---------------------------------------------------------------------------
// Main: fused GEMM (packed f32x2) + noise + bias + top-8 + softmax + scatter
// ---------------------------------------------------------------------------
__global__ __launch_bounds__(256, 1) void k_router(
    const float* __restrict__ X,      // [ntok, DIM]
    const float* __restrict__ W,      // [NE, DIM]
    const float* __restrict__ noise,  // [ntok, NE]
    float* __restrict__ out,
    int ntok)
{
    constexpr int XBUF = KB * XS_STRIDE;   // 4224 floats
    constexpr int WBUF = KB * WS_STRIDE;   // 2048 floats
    // 2*XBUF + WBUF = 10496 floats = 41984 bytes < 48KB static limit.
    // Epilogue logits tile (128*68 = 8704 floats) reuses this region.
    __shared__ __align__(16) float smem[2 * XBUF + WBUF];
    __shared__ float sLoads[NE];

    float* Ws = smem + 2 * XBUF;
    float* Ls = smem;

    const int tid = threadIdx.x;
    const int tx = tid & 15;    // expert-group 0..15 (4 experts each)
    const int ty = tid >> 4;    // token-group 0..15 (8 tokens each)
    const int t0 = blockIdx.x * TM;

    unsigned long long acc2[4][4];   // [token-pair][expert], 2 fp32 lanes each
    #pragma unroll
    for (int p = 0; p < 4; p++)
        #pragma unroll
        for (int j = 0; j < 4; j++) acc2[p][j] = 0ull;

    float4 xr[4], wr[2];   // prefetch registers

    // --- prefetch tile 0 ---
    #pragma unroll
    for (int u = 0; u < 4; u++) {
        int f = u * 256 + tid;
        xr[u] = *(const float4*)(X + (size_t)(t0 + (f >> 3)) * DIM + ((f & 7) * 4));
    }
    #pragma unroll
    for (int u = 0; u < 2; u++) {
        int f = u * 256 + tid;
        wr[u] = *(const float4*)(W + (size_t)(f >> 3) * DIM + ((f & 7) * 4));
    }
    // --- store tile 0 ---
    {
        float* Xn = smem;   // buffer 0
        #pragma unroll
        for (int u = 0; u < 4; u++) {
            int f = u * 256 + tid;
            int t = f >> 3, c4 = (f & 7) * 4;
            Xn[(c4 + 0) * XS_STRIDE + t] = xr[u].x;
            Xn[(c4 + 1) * XS_STRIDE + t] = xr[u].y;
            Xn[(c4 + 2) * XS_STRIDE + t] = xr[u].z;
            Xn[(c4 + 3) * XS_STRIDE + t] = xr[u].w;
        }
        #pragma unroll
        for (int u = 0; u < 2; u++) {
            int f = u * 256 + tid;
            int e = f >> 3, c4 = (f & 7) * 4;
            Ws[(c4 + 0) * WS_STRIDE + e] = wr[u].x;
            Ws[(c4 + 1) * WS_STRIDE + e] = wr[u].y;
            Ws[(c4 + 2) * WS_STRIDE + e] = wr[u].z;
            Ws[(c4 + 3) * WS_STRIDE + e] = wr[u].w;
        }
    }
    __syncthreads();

    for (int it = 0; it < NIT; ++it) {
        const float* Xs = smem + (it & 1) * XBUF;
        const bool more = (it + 1 < NIT);

        if (more) {   // issue global prefetch early; consumed after compute
            int kb = (it + 1) * KB;
            #pragma unroll
            for (int u = 0; u < 4; u++) {
                int f = u * 256 + tid;
                xr[u] = *(const float4*)(X + (size_t)(t0 + (f >> 3)) * DIM + kb + ((f & 7) * 4));
            }
            #pragma unroll
            for (int u = 0; u < 2; u++) {
                int f = u * 256 + tid;
                wr[u] = *(const float4*)(W + (size_t)(f >> 3) * DIM + kb + ((f & 7) * 4));
            }
        }

        #pragma unroll
        for (int k = 0; k < KB; k++) {
            float4 w4 = *(const float4*)&Ws[k * WS_STRIDE + tx * 4];
            unsigned long long w2[4];
            asm("mov.b64 %0, {%1, %1};" : "=l"(w2[0]) : "f"(w4.x));
            asm("mov.b64 %0, {%1, %1};" : "=l"(w2[1]) : "f"(w4.y));
            asm("mov.b64 %0, {%1, %1};" : "=l"(w2[2]) : "f"(w4.z));
            asm("mov.b64 %0, {%1, %1};" : "=l"(w2[3]) : "f"(w4.w));

            ulonglong2 xa = *(const ulonglong2*)&Xs[k * XS_STRIDE + ty * 8];
            ulonglong2 xb = *(const ulonglong2*)&Xs[k * XS_STRIDE + ty * 8 + 4];
            unsigned long long xp[4] = { xa.x, xa.y, xb.x, xb.y };

            #pragma unroll
            for (int p = 0; p < 4; p++)
                #pragma unroll
                for (int j = 0; j < 4; j++)
                    asm("fma.rn.f32x2 %0, %1, %2, %0;"
                        : "+l"(acc2[p][j]) : "l"(xp[p]), "l"(w2[j]));
        }

        if (more) {
            // X double-buffered: store to the other buffer, no sync needed first
            float* Xn = smem + ((it + 1) & 1) * XBUF;
            #pragma unroll
            for (int u = 0; u < 4; u++) {
                int f = u * 256 + tid;
                int t = f >> 3, c4 = (f & 7) * 4;
                Xn[(c4 + 0) * XS_STRIDE + t] = xr[u].x;
                Xn[(c4 + 1) * XS_STRIDE + t] = xr[u].y;
                Xn[(c4 + 2) * XS_STRIDE + t] = xr[u].z;
                Xn[(c4 + 3) * XS_STRIDE + t] = xr[u].w;
            }
            __syncthreads();   // everyone done reading Ws of this iter
            #pragma unroll
            for (int u = 0; u < 2; u++) {
                int f = u * 256 + tid;
                int e = f >> 3, c4 = (f & 7) * 4;
                Ws[(c4 + 0) * WS_STRIDE + e] = wr[u].x;
                Ws[(c4 + 1) * WS_STRIDE + e] = wr[u].y;
                Ws[(c4 + 2) * WS_STRIDE + e] = wr[u].z;
                Ws[(c4 + 3) * WS_STRIDE + e] = wr[u].w;
            }
            __syncthreads();   // Ws ready
        }
    }
    __syncthreads();   // mainloop smem reads complete before Ls overwrite

    // Epilogue part 1: logits = acc + 0.01*noise - bias  -> Ls (reuses smem)
    float4 bv = *(const float4*)(&g_bias[tx * 4]);
    #pragma unroll
    for (int p = 0; p < 4; p++) {
        int tA = ty * 8 + 2 * p;
        int tB = tA + 1;
        float lo[4], hi[4];
        #pragma unroll
        for (int j = 0; j < 4; j++)
            asm("mov.b64 {%0, %1}, %2;" : "=f"(lo[j]), "=f"(hi[j]) : "l"(acc2[p][j]));

        float4 nA = *(const float4*)(noise + (size_t)(t0 + tA) * NE + tx * 4);
        float4 nB = *(const float4*)(noise + (size_t)(t0 + tB) * NE + tx * 4);
        float4 lA, lB;
        lA.x = lo[0] + 0.01f * nA.x - bv.x;
        lA.y = lo[1] + 0.01f * nA.y - bv.y;
        lA.z = lo[2] + 0.01f * nA.z - bv.z;
        lA.w = lo[3] + 0.01f * nA.w - bv.w;
        lB.x = hi[0] + 0.01f * nB.x - bv.x;
        lB.y = hi[1] + 0.01f * nB.y - bv.y;
        lB.z = hi[2] + 0.01f * nB.z - bv.z;
        lB.w = hi[3] + 0.01f * nB.w - bv.w;
        *(float4*)&Ls[tA * LS_STRIDE + tx * 4] = lA;
        *(float4*)&Ls[tB * LS_STRIDE + tx * 4] = lB;
    }
    if (tid < NE) sLoads[tid] = 0.f;
    __syncthreads();

    // Epilogue part 2: per-token top-8 (stable: lowest index wins ties),
    // softmax over selected, write outputs, accumulate per-expert loads.
    if (tid < TM) {
        const int t = tid;
        float tv[TK];
        int   ti[TK];
        #pragma unroll
        for (int k = 0; k < TK; k++) { tv[k] = -INFINITY; ti[k] = -1; }

        for (int e = 0; e < NE; e++) {
            float v = Ls[t * LS_STRIDE + e];
            if (v > tv[TK - 1]) {           // strict >: earlier equal value stays
                int p = TK - 1;
                while (p > 0 && tv[p - 1] < v) {  // stop at equal -> stable insert
                    tv[p] = tv[p - 1];
                    ti[p] = ti[p - 1];
                    --p;
                }
                tv[p] = v;
                ti[p] = e;
            }
        }

        float m = tv[0];
        float w[TK];
        float s = 0.f;
        #pragma unroll
        for (int k = 0; k < TK; k++) { w[k] = expf(tv[k] - m); s += w[k]; }
        float inv = 1.0f / s;

        size_t gt = (size_t)(t0 + t);
        size_t woff = (size_t)ntok * TK;
        #pragma unroll
        for (int k = 0; k < TK; k++) {
            float wk = w[k] * inv;
            out[gt * TK + k]        = (float)ti[k];
            out[woff + gt * TK + k] = wk;
            atomicAdd(&sLoads[ti[k]], wk);
        }
    }
    __syncthreads();
    if (tid < NE) atomicAdd(&g_acc[tid], sLoads[tid]);
}

// ---------------------------------------------------------------------------
// Final: EMA load update + new bias strength
// ---------------------------------------------------------------------------
__global__ void k_final(const float* __restrict__ loads, float* __restrict__ out, int ntok)
{
    int e = threadIdx.x;
    size_t base = (size_t)ntok * TK * 2;
    float batch = g_acc[e] / (float)ntok;
    out[base + e] = 0.999f * loads[e] + (1.0f - 0.999f) * batch;
    if (e == 0) out[base + NE] = g_nbs;
}

// ---------------------------------------------------------------------------
// Launch
// ---------------------------------------------------------------------------
extern "C" void kernel_launch(void* const* d_in, const int* in_sizes, int n_in,
                              void* d_out, int out_size)
{
    const float* X     = (const float*)d_in[0];  // hidden_states [4,4096,2048]
    const float* W     = (const float*)d_in[1];  // router_w [64,2048]
    const float* loads = (const float*)d_in[2];  // expert_loads [64]
    const float* bs    = (const float*)d_in[3];  // bias_strength [1]
    const float* noise = (const float*)d_in[4];  // noise [16384,64]
    float* out = (float*)d_out;

    int ntok = in_sizes[0] / DIM;

    k_prep<<<1, NE>>>(loads, bs);
    k_router<<<ntok / TM, 256>>>(X, W, noise, out, ntok);
    k_final<<<1, NE>>>(loads, out, ntok);
}

// round 4
// speedup vs baseline: 1.7957x; 1.7957x over previous
#include <cuda_runtime.h>
#include <math.h>
#include <stdint.h>

#define NE   64
#define TK   8
#define DIM  2048
#define TM   128            // tokens per CTA
#define KB   32             // k per chunk
#define NCH  (DIM / KB)     // 64 chunks
#define RS   36             // smem row stride in words (32 data + 4 pad, conflict-free)

// per-stage smem layout in floats
#define XOFF  0
#define WHOFF (TM * RS)                 // 4608
#define WLOFF (WHOFF + NE * RS)         // 4608 + 2304
#define SSTR  (WLOFF + NE * RS)         // 9216 floats per stage
#define DYN_FLOATS (2 * SSTR)           // 18432 floats = 73728 B
#define LS_STRIDE 68

__device__ float g_whi[NE * DIM];
__device__ float g_wlo[NE * DIM];
__device__ __align__(16) float g_bias[NE];
__device__ float g_nbs;
__device__ float g_acc[NE];

static __device__ __forceinline__ float fhi(float x) {
    return __uint_as_float(__float_as_uint(x) & 0xFFFFE000u);
}

static __device__ __forceinline__ void mma8(float* c,
    uint32_t a0, uint32_t a1, uint32_t a2, uint32_t a3,
    uint32_t b0, uint32_t b1)
{
    asm volatile(
        "mma.sync.aligned.m16n8k8.row.col.f32.tf32.tf32.f32 "
        "{%0,%1,%2,%3}, {%4,%5,%6,%7}, {%8,%9}, {%0,%1,%2,%3};"
        : "+f"(c[0]), "+f"(c[1]), "+f"(c[2]), "+f"(c[3])
        : "r"(a0), "r"(a1), "r"(a2), "r"(a3), "r"(b0), "r"(b1));
}

// ---------------------------------------------------------------------------
// Setup: split W into tf32 hi/lo scratch (blocks 0..63), adaptive bias (block 64)
// ---------------------------------------------------------------------------
__global__ void k_setup(const float* __restrict__ W,
                        const float* __restrict__ loads,
                        const float* __restrict__ bs)
{
    __shared__ float s[NE], s2[NE];
    int b = blockIdx.x, tid = threadIdx.x;

    if (b < NE) {
        const float4* wr = (const float4*)(W + (size_t)b * DIM);
        float4* whi = (float4*)(g_whi + (size_t)b * DIM);
        float4* wlo = (float4*)(g_wlo + (size_t)b * DIM);
        #pragma unroll
        for (int u = 0; u < 2; u++) {
            int f = u * 256 + tid;
            float4 v = wr[f];
            float4 h, l;
            h.x = fhi(v.x); h.y = fhi(v.y); h.z = fhi(v.z); h.w = fhi(v.w);
            l.x = v.x - h.x; l.y = v.y - h.y; l.z = v.z - h.z; l.w = v.w - h.w;
            whi[f] = h;
            wlo[f] = l;
        }
    } else if (tid < NE) {
        int e = tid;
        s[e] = loads[e];
        __syncthreads();
        float sum = 0.f;
        #pragma unroll
        for (int i = 0; i < NE; i++) sum += s[i];
        sum = fmaxf(sum, 1e-8f);

        const float t = 1.0f / (float)NE;
        float q = s[e] / sum;
        s2[e] = t * (logf(t) - logf(fmaxf(q, 1e-8f)));
        __syncthreads();
        float kl = 0.f;
        #pragma unroll
        for (int i = 0; i < NE; i++) kl += s2[i];

        float adaptive = 1.0f / (1.0f + expf(-10.0f * kl));
        float nbs = 0.9f * bs[0] + 0.1f * adaptive;
        g_bias[e] = tanhf((q - t) * (float)NE) * nbs;
        g_acc[e] = 0.f;
        if (e == 0) g_nbs = nbs;
    }
}

// ---------------------------------------------------------------------------
// Router: 3xTF32 mma.sync GEMM + fused epilogue
// warp w: h = w&1 -> token half (64 tokens), ksw = w>>1 -> kstep within chunk
// ---------------------------------------------------------------------------
__global__ __launch_bounds__(256, 1) void k_router(
    const float* __restrict__ X,      // [ntok, DIM]
    const float* __restrict__ noise,  // [ntok, NE]
    float* __restrict__ out,
    int ntok)
{
    extern __shared__ float smem[];
    __shared__ float sLoads[NE];
    __shared__ float sBias[NE];

    const int tid  = threadIdx.x;
    const int lane = tid & 31;
    const int warp = tid >> 5;
    const int h    = warp & 1;
    const int ksw  = warp >> 1;
    const int g    = lane >> 2;
    const int tig  = lane & 3;
    const int t0   = blockIdx.x * TM;

    if (tid < NE) { sLoads[tid] = 0.f; sBias[tid] = g_bias[tid]; }

    float acc[4][8][4];
    #pragma unroll
    for (int i = 0; i < 4; i++)
        #pragma unroll
        for (int j = 0; j < 8; j++)
            #pragma unroll
            for (int q = 0; q < 4; q++) acc[i][j][q] = 0.f;

    float4 xr[4], wh[2], wl[2];

    // ---- prefetch + store chunk 0 ----
    #pragma unroll
    for (int u = 0; u < 4; u++) {
        int f = u * 256 + tid;
        xr[u] = *(const float4*)(X + (size_t)(t0 + (f >> 3)) * DIM + (f & 7) * 4);
    }
    #pragma unroll
    for (int u = 0; u < 2; u++) {
        int f = u * 256 + tid;
        wh[u] = *(const float4*)(g_whi + (size_t)(f >> 3) * DIM + (f & 7) * 4);
        wl[u] = *(const float4*)(g_wlo + (size_t)(f >> 3) * DIM + (f & 7) * 4);
    }
    {
        float* st = smem;   // stage 0
        #pragma unroll
        for (int u = 0; u < 4; u++) {
            int f = u * 256 + tid;
            *(float4*)&st[XOFF + (f >> 3) * RS + (f & 7) * 4] = xr[u];
        }
        #pragma unroll
        for (int u = 0; u < 2; u++) {
            int f = u * 256 + tid;
            *(float4*)&st[WHOFF + (f >> 3) * RS + (f & 7) * 4] = wh[u];
            *(float4*)&st[WLOFF + (f >> 3) * RS + (f & 7) * 4] = wl[u];
        }
    }
    __syncthreads();

    // ---- mainloop ----
    for (int c = 0; c < NCH; ++c) {
        const bool more = (c + 1 < NCH);
        if (more) {
            int kb = (c + 1) * KB;
            #pragma unroll
            for (int u = 0; u < 4; u++) {
                int f = u * 256 + tid;
                xr[u] = *(const float4*)(X + (size_t)(t0 + (f >> 3)) * DIM + kb + (f & 7) * 4);
            }
            #pragma unroll
            for (int u = 0; u < 2; u++) {
                int f = u * 256 + tid;
                wh[u] = *(const float4*)(g_whi + (size_t)(f >> 3) * DIM + kb + (f & 7) * 4);
                wl[u] = *(const float4*)(g_wlo + (size_t)(f >> 3) * DIM + kb + (f & 7) * 4);
            }
        }

        // ---- consume chunk c ----
        {
            const float* st = smem + (c & 1) * SSTR;
            const float* Xs = st + XOFF;
            const float* WHs = st + WHOFF;
            const float* WLs = st + WLOFF;
            const int kcol = ksw * 8;

            // B fragments for this warp's kstep (hi & lo), all 8 n-tiles
            uint32_t bh[8][2], bl[8][2];
            #pragma unroll
            for (int j = 0; j < 8; j++) {
                int br = (8 * j + g) * RS + kcol;
                bh[j][0] = __float_as_uint(WHs[br + tig]);
                bh[j][1] = __float_as_uint(WHs[br + tig + 4]);
                bl[j][0] = __float_as_uint(WLs[br + tig]);
                bl[j][1] = __float_as_uint(WLs[br + tig + 4]);
            }

            #pragma unroll
            for (int i = 0; i < 4; i++) {
                int ar = (64 * h + 16 * i + g) * RS + kcol;
                float a0 = Xs[ar + tig];
                float a1 = Xs[ar + 8 * RS + tig];
                float a2 = Xs[ar + tig + 4];
                float a3 = Xs[ar + 8 * RS + tig + 4];
                float h0 = fhi(a0), h1 = fhi(a1), h2 = fhi(a2), h3 = fhi(a3);
                uint32_t ah0 = __float_as_uint(h0), ah1 = __float_as_uint(h1);
                uint32_t ah2 = __float_as_uint(h2), ah3 = __float_as_uint(h3);
                uint32_t al0 = __float_as_uint(a0 - h0), al1 = __float_as_uint(a1 - h1);
                uint32_t al2 = __float_as_uint(a2 - h2), al3 = __float_as_uint(a3 - h3);

                #pragma unroll
                for (int j = 0; j < 8; j++) {
                    mma8(acc[i][j], ah0, ah1, ah2, ah3, bh[j][0], bh[j][1]);
                    mma8(acc[i][j], ah0, ah1, ah2, ah3, bl[j][0], bl[j][1]);
                    mma8(acc[i][j], al0, al1, al2, al3, bh[j][0], bh[j][1]);
                }
            }
        }

        // ---- store chunk c+1 into the other stage ----
        if (more) {
            float* st = smem + ((c + 1) & 1) * SSTR;
            #pragma unroll
            for (int u = 0; u < 4; u++) {
                int f = u * 256 + tid;
                *(float4*)&st[XOFF + (f >> 3) * RS + (f & 7) * 4] = xr[u];
            }
            #pragma unroll
            for (int u = 0; u < 2; u++) {
                int f = u * 256 + tid;
                *(float4*)&st[WHOFF + (f >> 3) * RS + (f & 7) * 4] = wh[u];
                *(float4*)&st[WLOFF + (f >> 3) * RS + (f & 7) * 4] = wl[u];
            }
            __syncthreads();
        }
    }
    __syncthreads();   // all compute done before smem reuse

    // ---- cross-kstep reduction into logits tile Ls[128][68] ----
    float* Ls = smem;
    for (int idx = tid; idx < TM * LS_STRIDE; idx += 256) Ls[idx] = 0.f;
    __syncthreads();

    for (int round = 0; round < 4; round++) {
        if (ksw == round) {
            #pragma unroll
            for (int i = 0; i < 4; i++) {
                int rt = 64 * h + 16 * i + g;
                #pragma unroll
                for (int j = 0; j < 8; j++) {
                    int cc = 8 * j + 2 * tig;
                    Ls[rt * LS_STRIDE + cc]           += acc[i][j][0];
                    Ls[rt * LS_STRIDE + cc + 1]       += acc[i][j][1];
                    Ls[(rt + 8) * LS_STRIDE + cc]     += acc[i][j][2];
                    Ls[(rt + 8) * LS_STRIDE + cc + 1] += acc[i][j][3];
                }
            }
        }
        __syncthreads();
    }

    // ---- epilogue: per-token top-8 + softmax + load scatter ----
    if (tid < TM) {
        const int t = tid;
        size_t gt = (size_t)(t0 + t);

        float nzf[NE];
        const float4* nr = (const float4*)(noise + gt * NE);
        #pragma unroll
        for (int i = 0; i < 16; i++) {
            float4 v = nr[i];
            nzf[4 * i + 0] = v.x; nzf[4 * i + 1] = v.y;
            nzf[4 * i + 2] = v.z; nzf[4 * i + 3] = v.w;
        }

        float tv[TK];
        int   ti_[TK];
        #pragma unroll
        for (int k = 0; k < TK; k++) { tv[k] = -INFINITY; ti_[k] = -1; }

        for (int e = 0; e < NE; e++) {
            float v = Ls[t * LS_STRIDE + e] + 0.01f * nzf[e] - sBias[e];
            if (v > tv[TK - 1]) {                 // strict >: earlier equal value stays
                int p = TK - 1;
                while (p > 0 && tv[p - 1] < v) {  // stop at equal -> stable insert
                    tv[p] = tv[p - 1];
                    ti_[p] = ti_[p - 1];
                    --p;
                }
                tv[p] = v;
                ti_[p] = e;
            }
        }

        float m = tv[0];
        float w[TK];
        float ssum = 0.f;
        #pragma unroll
        for (int k = 0; k < TK; k++) { w[k] = expf(tv[k] - m); ssum += w[k]; }
        float inv = 1.0f / ssum;

        size_t woff = (size_t)ntok * TK;
        #pragma unroll
        for (int k = 0; k < TK; k++) {
            float wk = w[k] * inv;
            out[gt * TK + k]        = (float)ti_[k];
            out[woff + gt * TK + k] = wk;
            atomicAdd(&sLoads[ti_[k]], wk);
        }
    }
    __syncthreads();
    if (tid < NE) atomicAdd(&g_acc[tid], sLoads[tid]);
}

// ---------------------------------------------------------------------------
// Final: EMA load update + new bias strength
// ---------------------------------------------------------------------------
__global__ void k_final(const float* __restrict__ loads, float* __restrict__ out, int ntok)
{
    int e = threadIdx.x;
    size_t base = (size_t)ntok * TK * 2;
    float batch = g_acc[e] / (float)ntok;
    out[base + e] = 0.999f * loads[e] + (1.0f - 0.999f) * batch;
    if (e == 0) out[base + NE] = g_nbs;
}

// ---------------------------------------------------------------------------
// Launch
// ---------------------------------------------------------------------------
extern "C" void kernel_launch(void* const* d_in, const int* in_sizes, int n_in,
                              void* d_out, int out_size)
{
    const float* X     = (const float*)d_in[0];  // hidden_states [4,4096,2048]
    const float* W     = (const float*)d_in[1];  // router_w [64,2048]
    const float* loads = (const float*)d_in[2];  // expert_loads [64]
    const float* bs    = (const float*)d_in[3];  // bias_strength [1]
    const float* noise = (const float*)d_in[4];  // noise [16384,64]
    float* out = (float*)d_out;

    int ntok = in_sizes[0] / DIM;

    static int cfg = 0;
    if (!cfg) {
        cudaFuncSetAttribute(k_router, cudaFuncAttributeMaxDynamicSharedMemorySize,
                             DYN_FLOATS * 4);
        cfg = 1;
    }

    k_setup<<<NE + 1, 256>>>(W, loads, bs);
    k_router<<<ntok / TM, 256, DYN_FLOATS * 4>>>(X, noise, out, ntok);
    k_final<<<1, NE>>>(loads, out, ntok);
}